// round 1
// baseline (speedup 1.0000x reference)
#include <cuda_runtime.h>
#include <cuda_bf16.h>

#define NN 8192
#define BB 2
#define COLS_PER_BLOCK 1024   // 256 threads * float4
#define ROWS_PER_BLOCK 64

// Scratch (allocation-free rule: __device__ globals)
__device__ float g_deg[NN];
__device__ float g_z[BB * NN];

// ---------------------------------------------------------------------------
// K1: zero the accumulators (graph is replayed; must re-zero every launch)
// ---------------------------------------------------------------------------
__global__ void zero_kernel() {
    int i = blockIdx.x * blockDim.x + threadIdx.x;
    if (i < NN) g_deg[i] = 0.0f;
    if (i < BB * NN) g_z[i] = 0.0f;
}

// ---------------------------------------------------------------------------
// K2: column sums  deg[c] = sum_r DSM[r,c]
// Block: 256 threads, covers 1024 consecutive columns (float4 per thread)
// and ROWS_PER_BLOCK rows. Partials merged with atomicAdd (REDG).
// ---------------------------------------------------------------------------
__global__ void __launch_bounds__(256) colsum_kernel(const float* __restrict__ dsm) {
    const int c0 = blockIdx.x * COLS_PER_BLOCK + threadIdx.x * 4;
    const int r0 = blockIdx.y * ROWS_PER_BLOCK;

    float ax = 0.f, ay = 0.f, az = 0.f, aw = 0.f;
    const float* p = dsm + (size_t)r0 * NN + c0;
    #pragma unroll 8
    for (int r = 0; r < ROWS_PER_BLOCK; ++r) {
        float4 v = *(const float4*)p;
        ax += v.x; ay += v.y; az += v.z; aw += v.w;
        p += NN;
    }
    atomicAdd(&g_deg[c0 + 0], ax);
    atomicAdd(&g_deg[c0 + 1], ay);
    atomicAdd(&g_deg[c0 + 2], az);
    atomicAdd(&g_deg[c0 + 3], aw);
}

// ---------------------------------------------------------------------------
// K3: z_raw[b,c] = sum_r (dinv[r]*x[b,r]) * DSM[r,c]   for b = 0,1 in one pass
// ---------------------------------------------------------------------------
__global__ void __launch_bounds__(256) matvec_kernel(const float* __restrict__ dsm,
                                                     const float* __restrict__ x) {
    __shared__ float s0[ROWS_PER_BLOCK];
    __shared__ float s1[ROWS_PER_BLOCK];

    const int r0 = blockIdx.y * ROWS_PER_BLOCK;
    const int t  = threadIdx.x;

    // Stage dinv[r]*x[b,r] for this row chunk (2*64 = 128 values)
    if (t < 2 * ROWS_PER_BLOCK) {
        int b = t / ROWS_PER_BLOCK;
        int i = t % ROWS_PER_BLOCK;
        float d  = g_deg[r0 + i];
        float di = (d > 0.f) ? rsqrtf(d) : 0.f;
        float v  = di * x[b * NN + r0 + i];
        if (b == 0) s0[i] = v; else s1[i] = v;
    }
    __syncthreads();

    const int c0 = blockIdx.x * COLS_PER_BLOCK + threadIdx.x * 4;
    float a0x = 0.f, a0y = 0.f, a0z = 0.f, a0w = 0.f;
    float a1x = 0.f, a1y = 0.f, a1z = 0.f, a1w = 0.f;

    const float* p = dsm + (size_t)r0 * NN + c0;
    #pragma unroll 8
    for (int r = 0; r < ROWS_PER_BLOCK; ++r) {
        float4 v = *(const float4*)p;
        float w0 = s0[r];
        float w1 = s1[r];
        a0x += v.x * w0; a0y += v.y * w0; a0z += v.z * w0; a0w += v.w * w0;
        a1x += v.x * w1; a1y += v.y * w1; a1z += v.z * w1; a1w += v.w * w1;
        p += NN;
    }
    atomicAdd(&g_z[c0 + 0], a0x);
    atomicAdd(&g_z[c0 + 1], a0y);
    atomicAdd(&g_z[c0 + 2], a0z);
    atomicAdd(&g_z[c0 + 3], a0w);
    atomicAdd(&g_z[NN + c0 + 0], a1x);
    atomicAdd(&g_z[NN + c0 + 1], a1y);
    atomicAdd(&g_z[NN + c0 + 2], a1z);
    atomicAdd(&g_z[NN + c0 + 3], a1w);
}

// ---------------------------------------------------------------------------
// K4: epilogue. h2[b,c] = relu chain; s[b] from mean; state value; and the
// action_prob output, which is softmax over a size-1 axis == 1.0 exactly.
// ---------------------------------------------------------------------------
__global__ void __launch_bounds__(256) finalize_kernel(
    const float* __restrict__ w1,  const float* __restrict__ b1,
    const float* __restrict__ lw1, const float* __restrict__ lb1,
    const float* __restrict__ lw2, const float* __restrict__ lb2,
    const float* __restrict__ w2,  const float* __restrict__ b2,
    const float* __restrict__ w3,  const float* __restrict__ b3,
    const float* __restrict__ wv,  const float* __restrict__ bv,
    float* __restrict__ out, int out_size)
{
    __shared__ float red0[8];
    __shared__ float red1[8];

    const float W1 = w1[0],  B1 = b1[0];
    const float L1 = lw1[0], LB1 = lb1[0];
    const float L2 = lw2[0], LB2 = lb2[0];

    float sum0 = 0.f, sum1 = 0.f;
    for (int c = threadIdx.x; c < NN; c += blockDim.x) {
        float d  = g_deg[c];
        float di = (d > 0.f) ? rsqrtf(d) : 0.f;
        float h0 = fmaxf(g_z[c]      * di * W1 + B1, 0.f);
        float h1 = fmaxf(g_z[NN + c] * di * W1 + B1, 0.f);
        h0 = fmaxf(h0 * L1 + LB1, 0.f);
        h1 = fmaxf(h1 * L1 + LB1, 0.f);
        h0 = fmaxf(h0 * L2 + LB2, 0.f);
        h1 = fmaxf(h1 * L2 + LB2, 0.f);
        sum0 += h0;
        sum1 += h1;
    }
    // warp reduce
    for (int o = 16; o > 0; o >>= 1) {
        sum0 += __shfl_xor_sync(0xFFFFFFFFu, sum0, o);
        sum1 += __shfl_xor_sync(0xFFFFFFFFu, sum1, o);
    }
    int warp = threadIdx.x >> 5;
    int lane = threadIdx.x & 31;
    if (lane == 0) { red0[warp] = sum0; red1[warp] = sum1; }
    __syncthreads();

    if (threadIdx.x == 0) {
        float t0 = 0.f, t1 = 0.f;
        #pragma unroll
        for (int w = 0; w < 8; ++w) { t0 += red0[w]; t1 += red1[w]; }
        const float inv_n = 1.0f / (float)NN;
        // _gcn_uniform #1: m = mean(h2*w2)+b2, relu
        float m0 = fmaxf(t0 * inv_n * w2[0] + b2[0], 0.f);
        float m1 = fmaxf(t1 * inv_n * w2[0] + b2[0], 0.f);
        // _gcn_uniform #2: mean of a constant is itself
        float s0v = fmaxf(m0 * w3[0] + b3[0], 0.f);
        float s1v = fmaxf(m1 * w3[0] + b3[0], 0.f);
        float v   = fmaxf(s0v, s1v);
        float sv  = v * wv[0] + bv[0];
        if (out_size > BB * NN) out[BB * NN] = sv;
    }

    // action_prob: softmax over axis of size 1 -> exactly 1.0 everywhere
    for (int i = threadIdx.x; i < BB * NN && i < out_size; i += blockDim.x)
        out[i] = 1.0f;
}

// ---------------------------------------------------------------------------
extern "C" void kernel_launch(void* const* d_in, const int* in_sizes, int n_in,
                              void* d_out, int out_size) {
    const float* x   = (const float*)d_in[0];
    const float* dsm = (const float*)d_in[1];
    const float* w1  = (const float*)d_in[2];
    const float* b1  = (const float*)d_in[3];
    const float* lw1 = (const float*)d_in[4];
    const float* lb1 = (const float*)d_in[5];
    const float* lw2 = (const float*)d_in[6];
    const float* lb2 = (const float*)d_in[7];
    const float* w2  = (const float*)d_in[8];
    const float* b2  = (const float*)d_in[9];
    const float* w3  = (const float*)d_in[10];
    const float* b3  = (const float*)d_in[11];
    // wa (d_in[12]) / ba (d_in[13]) cancel inside the size-1 softmax
    const float* wv  = (const float*)d_in[14];
    const float* bv  = (const float*)d_in[15];
    float* out = (float*)d_out;

    zero_kernel<<<(BB * NN + 255) / 256, 256>>>();

    dim3 grid(NN / COLS_PER_BLOCK, NN / ROWS_PER_BLOCK);  // (8, 128)
    colsum_kernel<<<grid, 256>>>(dsm);
    matvec_kernel<<<grid, 256>>>(dsm, x);

    finalize_kernel<<<1, 256>>>(w1, b1, lw1, lb1, lw2, lb2,
                                w2, b2, w3, b3, wv, bv, out, out_size);
}

// round 6
// speedup vs baseline: 1.1180x; 1.1180x over previous
#include <cuda_runtime.h>
#include <cuda_bf16.h>

#define NN 8192
#define BB 2
#define COLS_PER_BLOCK 1024   // 256 threads * float4
#define ROWS_PER_BLOCK 64

// Scratch (allocation-free rule: __device__ globals)
__device__ float g_deg[NN];
__device__ float g_z[BB * NN];
__device__ float g_sums[BB];

// ---------------------------------------------------------------------------
// K0: init. Zero scratch AND fill the action_prob output with 1.0f
// (softmax over a size-1 axis is exactly 1). Wide grid so it's bandwidth-
// bound, not latency-bound.
// ---------------------------------------------------------------------------
__global__ void __launch_bounds__(256) init_kernel(float* __restrict__ out, int out_size) {
    int i = blockIdx.x * blockDim.x + threadIdx.x;
    if (i < NN) g_deg[i] = 0.0f;
    if (i < BB * NN) {
        g_z[i] = 0.0f;
        if (i < out_size) out[i] = 1.0f;
    }
    if (i < BB) g_sums[i] = 0.0f;
}

// ---------------------------------------------------------------------------
// K1: column sums  deg[c] = sum_r DSM[r,c]
// ---------------------------------------------------------------------------
__global__ void __launch_bounds__(256) colsum_kernel(const float* __restrict__ dsm) {
    const int c0 = blockIdx.x * COLS_PER_BLOCK + threadIdx.x * 4;
    const int r0 = blockIdx.y * ROWS_PER_BLOCK;

    float ax = 0.f, ay = 0.f, az = 0.f, aw = 0.f;
    const float* p = dsm + (size_t)r0 * NN + c0;
    #pragma unroll 8
    for (int r = 0; r < ROWS_PER_BLOCK; ++r) {
        float4 v = *(const float4*)p;
        ax += v.x; ay += v.y; az += v.z; aw += v.w;
        p += NN;
    }
    atomicAdd(&g_deg[c0 + 0], ax);
    atomicAdd(&g_deg[c0 + 1], ay);
    atomicAdd(&g_deg[c0 + 2], az);
    atomicAdd(&g_deg[c0 + 3], aw);
}

// ---------------------------------------------------------------------------
// K2: z[b,c] = sum_r (dinv[r]*x[b,r]) * DSM[r,c]  for b = 0,1 in one pass
// ---------------------------------------------------------------------------
__global__ void __launch_bounds__(256) matvec_kernel(const float* __restrict__ dsm,
                                                     const float* __restrict__ x) {
    __shared__ float s0[ROWS_PER_BLOCK];
    __shared__ float s1[ROWS_PER_BLOCK];

    const int r0 = blockIdx.y * ROWS_PER_BLOCK;
    const int t  = threadIdx.x;

    if (t < 2 * ROWS_PER_BLOCK) {
        int b = t / ROWS_PER_BLOCK;
        int i = t % ROWS_PER_BLOCK;
        float d  = g_deg[r0 + i];
        float di = (d > 0.f) ? rsqrtf(d) : 0.f;
        float v  = di * x[b * NN + r0 + i];
        if (b == 0) s0[i] = v; else s1[i] = v;
    }
    __syncthreads();

    const int c0 = blockIdx.x * COLS_PER_BLOCK + threadIdx.x * 4;
    float a0x = 0.f, a0y = 0.f, a0z = 0.f, a0w = 0.f;
    float a1x = 0.f, a1y = 0.f, a1z = 0.f, a1w = 0.f;

    const float* p = dsm + (size_t)r0 * NN + c0;
    #pragma unroll 8
    for (int r = 0; r < ROWS_PER_BLOCK; ++r) {
        float4 v = *(const float4*)p;
        float w0 = s0[r];
        float w1 = s1[r];
        a0x += v.x * w0; a0y += v.y * w0; a0z += v.z * w0; a0w += v.w * w0;
        a1x += v.x * w1; a1y += v.y * w1; a1z += v.z * w1; a1w += v.w * w1;
        p += NN;
    }
    atomicAdd(&g_z[c0 + 0], a0x);
    atomicAdd(&g_z[c0 + 1], a0y);
    atomicAdd(&g_z[c0 + 2], a0z);
    atomicAdd(&g_z[c0 + 3], a0w);
    atomicAdd(&g_z[NN + c0 + 0], a1x);
    atomicAdd(&g_z[NN + c0 + 1], a1y);
    atomicAdd(&g_z[NN + c0 + 2], a1z);
    atomicAdd(&g_z[NN + c0 + 3], a1w);
}

// ---------------------------------------------------------------------------
// K3: multi-block reduction of the relu chain over all 8192 columns.
// 32 blocks x 256 threads = 8192 threads, one column each; per-block
// tree-reduce, then one atomicAdd per (block, batch).
// ---------------------------------------------------------------------------
__global__ void __launch_bounds__(256) reduce_kernel(
    const float* __restrict__ w1,  const float* __restrict__ b1,
    const float* __restrict__ lw1, const float* __restrict__ lb1,
    const float* __restrict__ lw2, const float* __restrict__ lb2)
{
    __shared__ float red0[8];
    __shared__ float red1[8];

    const float W1 = w1[0],  B1 = b1[0];
    const float L1 = lw1[0], LB1 = lb1[0];
    const float L2 = lw2[0], LB2 = lb2[0];

    const int c = blockIdx.x * blockDim.x + threadIdx.x;  // 0..8191 exactly

    float d  = g_deg[c];
    float di = (d > 0.f) ? rsqrtf(d) : 0.f;
    float h0 = fmaxf(g_z[c]      * di * W1 + B1, 0.f);
    float h1 = fmaxf(g_z[NN + c] * di * W1 + B1, 0.f);
    h0 = fmaxf(h0 * L1 + LB1, 0.f);
    h1 = fmaxf(h1 * L1 + LB1, 0.f);
    h0 = fmaxf(h0 * L2 + LB2, 0.f);
    h1 = fmaxf(h1 * L2 + LB2, 0.f);

    for (int o = 16; o > 0; o >>= 1) {
        h0 += __shfl_xor_sync(0xFFFFFFFFu, h0, o);
        h1 += __shfl_xor_sync(0xFFFFFFFFu, h1, o);
    }
    int warp = threadIdx.x >> 5;
    int lane = threadIdx.x & 31;
    if (lane == 0) { red0[warp] = h0; red1[warp] = h1; }
    __syncthreads();

    if (threadIdx.x < 2) {
        float* red = (threadIdx.x == 0) ? red0 : red1;
        float t = 0.f;
        #pragma unroll
        for (int w = 0; w < 8; ++w) t += red[w];
        atomicAdd(&g_sums[threadIdx.x], t);
    }
}

// ---------------------------------------------------------------------------
// K4: final scalar -> out[16384]
// ---------------------------------------------------------------------------
__global__ void scalar_kernel(
    const float* __restrict__ w2, const float* __restrict__ b2,
    const float* __restrict__ w3, const float* __restrict__ b3,
    const float* __restrict__ wv, const float* __restrict__ bv,
    float* __restrict__ out, int out_size)
{
    if (threadIdx.x == 0 && out_size > BB * NN) {
        const float inv_n = 1.0f / (float)NN;
        float m0 = fmaxf(g_sums[0] * inv_n * w2[0] + b2[0], 0.f);
        float m1 = fmaxf(g_sums[1] * inv_n * w2[0] + b2[0], 0.f);
        float s0v = fmaxf(m0 * w3[0] + b3[0], 0.f);
        float s1v = fmaxf(m1 * w3[0] + b3[0], 0.f);
        float v   = fmaxf(s0v, s1v);
        out[BB * NN] = v * wv[0] + bv[0];
    }
}

// ---------------------------------------------------------------------------
extern "C" void kernel_launch(void* const* d_in, const int* in_sizes, int n_in,
                              void* d_out, int out_size) {
    const float* x   = (const float*)d_in[0];
    const float* dsm = (const float*)d_in[1];
    const float* w1  = (const float*)d_in[2];
    const float* b1  = (const float*)d_in[3];
    const float* lw1 = (const float*)d_in[4];
    const float* lb1 = (const float*)d_in[5];
    const float* lw2 = (const float*)d_in[6];
    const float* lb2 = (const float*)d_in[7];
    const float* w2  = (const float*)d_in[8];
    const float* b2  = (const float*)d_in[9];
    const float* w3  = (const float*)d_in[10];
    const float* b3  = (const float*)d_in[11];
    // wa (d_in[12]) / ba (d_in[13]) cancel inside the size-1 softmax
    const float* wv  = (const float*)d_in[14];
    const float* bv  = (const float*)d_in[15];
    float* out = (float*)d_out;

    init_kernel<<<(BB * NN + 255) / 256, 256>>>(out, out_size);

    dim3 grid(NN / COLS_PER_BLOCK, NN / ROWS_PER_BLOCK);  // (8, 128)
    colsum_kernel<<<grid, 256>>>(dsm);
    matvec_kernel<<<grid, 256>>>(dsm, x);

    reduce_kernel<<<NN / 256, 256>>>(w1, b1, lw1, lb1, lw2, lb2);
    scalar_kernel<<<1, 32>>>(w2, b2, w3, b3, wv, bv, out, out_size);
}

// round 7
// speedup vs baseline: 1.3217x; 1.1822x over previous
#include <cuda_runtime.h>
#include <cuda_bf16.h>

#define NN 8192
#define BB 2
#define COLS_PER_BLOCK 1024   // 256 threads * float4
#define ROWS_PER_BLOCK 128

// Scratch (allocation-free rule: __device__ globals)
__device__ float g_deg[NN];
__device__ float g_z[BB * NN];
__device__ float g_sums[BB];
__device__ unsigned int g_done;

// ---------------------------------------------------------------------------
// K0: init. Zero scratch AND fill the action_prob output with 1.0f
// (softmax over a size-1 axis is exactly 1).
// ---------------------------------------------------------------------------
__global__ void __launch_bounds__(256) init_kernel(float* __restrict__ out, int out_size) {
    int i = blockIdx.x * blockDim.x + threadIdx.x;
    if (i < NN) g_deg[i] = 0.0f;
    if (i < BB * NN) {
        g_z[i] = 0.0f;
        if (i < out_size) out[i] = 1.0f;
    }
    if (i == 0) { g_sums[0] = 0.0f; g_sums[1] = 0.0f; g_done = 0u; }
}

// ---------------------------------------------------------------------------
// K1: column sums  deg[c] = sum_r DSM[r,c].  Streaming loads (__ldcs):
// DSM (268MB) has zero reuse across its two passes (L2 is 126MB).
// ---------------------------------------------------------------------------
__global__ void __launch_bounds__(256) colsum_kernel(const float* __restrict__ dsm) {
    const int c0 = blockIdx.x * COLS_PER_BLOCK + threadIdx.x * 4;
    const int r0 = blockIdx.y * ROWS_PER_BLOCK;

    float ax = 0.f, ay = 0.f, az = 0.f, aw = 0.f;
    const float4* p = (const float4*)(dsm + (size_t)r0 * NN + c0);
    #pragma unroll 8
    for (int r = 0; r < ROWS_PER_BLOCK; ++r) {
        float4 v = __ldcs(p);
        ax += v.x; ay += v.y; az += v.z; aw += v.w;
        p += NN / 4;
    }
    atomicAdd(&g_deg[c0 + 0], ax);
    atomicAdd(&g_deg[c0 + 1], ay);
    atomicAdd(&g_deg[c0 + 2], az);
    atomicAdd(&g_deg[c0 + 3], aw);
}

// ---------------------------------------------------------------------------
// K2: z[b,c] = sum_r (dinv[r]*x[b,r]) * DSM[r,c]  for b = 0,1 in one pass
// ---------------------------------------------------------------------------
__global__ void __launch_bounds__(256) matvec_kernel(const float* __restrict__ dsm,
                                                     const float* __restrict__ x) {
    __shared__ float s0[ROWS_PER_BLOCK];
    __shared__ float s1[ROWS_PER_BLOCK];

    const int r0 = blockIdx.y * ROWS_PER_BLOCK;
    const int t  = threadIdx.x;

    // Stage dinv[r]*x[b,r] for this row chunk (2*128 = 256 values)
    {
        int b = t / ROWS_PER_BLOCK;      // 0 or 1
        int i = t % ROWS_PER_BLOCK;
        float d  = g_deg[r0 + i];
        float di = (d > 0.f) ? rsqrtf(d) : 0.f;
        float v  = di * x[b * NN + r0 + i];
        if (b == 0) s0[i] = v; else s1[i] = v;
    }
    __syncthreads();

    const int c0 = blockIdx.x * COLS_PER_BLOCK + threadIdx.x * 4;
    float a0x = 0.f, a0y = 0.f, a0z = 0.f, a0w = 0.f;
    float a1x = 0.f, a1y = 0.f, a1z = 0.f, a1w = 0.f;

    const float4* p = (const float4*)(dsm + (size_t)r0 * NN + c0);
    #pragma unroll 8
    for (int r = 0; r < ROWS_PER_BLOCK; ++r) {
        float4 v = __ldcs(p);
        float w0 = s0[r];
        float w1 = s1[r];
        a0x += v.x * w0; a0y += v.y * w0; a0z += v.z * w0; a0w += v.w * w0;
        a1x += v.x * w1; a1y += v.y * w1; a1z += v.z * w1; a1w += v.w * w1;
        p += NN / 4;
    }
    atomicAdd(&g_z[c0 + 0], a0x);
    atomicAdd(&g_z[c0 + 1], a0y);
    atomicAdd(&g_z[c0 + 2], a0z);
    atomicAdd(&g_z[c0 + 3], a0w);
    atomicAdd(&g_z[NN + c0 + 0], a1x);
    atomicAdd(&g_z[NN + c0 + 1], a1y);
    atomicAdd(&g_z[NN + c0 + 2], a1z);
    atomicAdd(&g_z[NN + c0 + 3], a1w);
}

// ---------------------------------------------------------------------------
// K3: fused reduction + final scalar (last-block-done pattern).
// 32 blocks x 256 threads = 8192 threads, one column each. After the
// per-block atomicAdd, the last block to finish computes the state value.
// ---------------------------------------------------------------------------
__global__ void __launch_bounds__(256) reduce_finalize_kernel(
    const float* __restrict__ w1,  const float* __restrict__ b1,
    const float* __restrict__ lw1, const float* __restrict__ lb1,
    const float* __restrict__ lw2, const float* __restrict__ lb2,
    const float* __restrict__ w2,  const float* __restrict__ b2,
    const float* __restrict__ w3,  const float* __restrict__ b3,
    const float* __restrict__ wv,  const float* __restrict__ bv,
    float* __restrict__ out, int out_size)
{
    __shared__ float red0[8];
    __shared__ float red1[8];
    __shared__ bool  last;

    const float W1 = w1[0],  B1 = b1[0];
    const float L1 = lw1[0], LB1 = lb1[0];
    const float L2 = lw2[0], LB2 = lb2[0];

    const int c = blockIdx.x * blockDim.x + threadIdx.x;  // 0..8191 exactly

    float d  = g_deg[c];
    float di = (d > 0.f) ? rsqrtf(d) : 0.f;
    float h0 = fmaxf(g_z[c]      * di * W1 + B1, 0.f);
    float h1 = fmaxf(g_z[NN + c] * di * W1 + B1, 0.f);
    h0 = fmaxf(h0 * L1 + LB1, 0.f);
    h1 = fmaxf(h1 * L1 + LB1, 0.f);
    h0 = fmaxf(h0 * L2 + LB2, 0.f);
    h1 = fmaxf(h1 * L2 + LB2, 0.f);

    for (int o = 16; o > 0; o >>= 1) {
        h0 += __shfl_xor_sync(0xFFFFFFFFu, h0, o);
        h1 += __shfl_xor_sync(0xFFFFFFFFu, h1, o);
    }
    int warp = threadIdx.x >> 5;
    int lane = threadIdx.x & 31;
    if (lane == 0) { red0[warp] = h0; red1[warp] = h1; }
    __syncthreads();

    if (threadIdx.x == 0) {
        float t0 = 0.f, t1 = 0.f;
        #pragma unroll
        for (int w = 0; w < 8; ++w) { t0 += red0[w]; t1 += red1[w]; }
        atomicAdd(&g_sums[0], t0);
        atomicAdd(&g_sums[1], t1);
        __threadfence();
        unsigned int prev = atomicAdd(&g_done, 1u);
        last = (prev == gridDim.x - 1);
    }
    __syncthreads();

    if (last && threadIdx.x == 0 && out_size > BB * NN) {
        const float inv_n = 1.0f / (float)NN;
        float m0 = fmaxf(g_sums[0] * inv_n * w2[0] + b2[0], 0.f);
        float m1 = fmaxf(g_sums[1] * inv_n * w2[0] + b2[0], 0.f);
        float s0v = fmaxf(m0 * w3[0] + b3[0], 0.f);
        float s1v = fmaxf(m1 * w3[0] + b3[0], 0.f);
        float v   = fmaxf(s0v, s1v);
        out[BB * NN] = v * wv[0] + bv[0];
    }
}

// ---------------------------------------------------------------------------
extern "C" void kernel_launch(void* const* d_in, const int* in_sizes, int n_in,
                              void* d_out, int out_size) {
    const float* x   = (const float*)d_in[0];
    const float* dsm = (const float*)d_in[1];
    const float* w1  = (const float*)d_in[2];
    const float* b1  = (const float*)d_in[3];
    const float* lw1 = (const float*)d_in[4];
    const float* lb1 = (const float*)d_in[5];
    const float* lw2 = (const float*)d_in[6];
    const float* lb2 = (const float*)d_in[7];
    const float* w2  = (const float*)d_in[8];
    const float* b2  = (const float*)d_in[9];
    const float* w3  = (const float*)d_in[10];
    const float* b3  = (const float*)d_in[11];
    // wa (d_in[12]) / ba (d_in[13]) cancel inside the size-1 softmax
    const float* wv  = (const float*)d_in[14];
    const float* bv  = (const float*)d_in[15];
    float* out = (float*)d_out;

    init_kernel<<<(BB * NN + 255) / 256, 256>>>(out, out_size);

    dim3 grid(NN / COLS_PER_BLOCK, NN / ROWS_PER_BLOCK);  // (8, 64) = 512 blocks
    colsum_kernel<<<grid, 256>>>(dsm);
    matvec_kernel<<<grid, 256>>>(dsm, x);

    reduce_finalize_kernel<<<NN / 256, 256>>>(w1, b1, lw1, lb1, lw2, lb2,
                                              w2, b2, w3, b3, wv, bv, out, out_size);
}